// round 2
// baseline (speedup 1.0000x reference)
#include <cuda_runtime.h>
#include <cstdint>

// Problem constants (fixed shapes per reference)
#define NG   16      // B * n_w = 4*4 graphs
#define NPTS 2048
#define DIM  128
#define TS   128     // gram tile size
#define NT   (NPTS/TS)   // 16 tiles per side
#define KC   16      // k chunk
#define THRESH 1e-5f

// Scratch (static device globals; no allocations anywhere)
__device__ float g_Xb[(size_t)NG*NPTS*DIM];          // 16.8 MB
__device__ float g_diag[NG*NPTS];
__device__ float g_colsum[NG*NPTS];
__device__ float g_K[(size_t)NG*NPTS*NPTS];          // 256 MB
__device__ float g_v[9][NG*NPTS];

// ---------------------------------------------------------------------------
// Kernel 1: Xb = pc * alpha, diag = ||Xb_row||^2, zero colsum, v0 = 1/N
// grid = NG*NPTS blocks, 128 threads (one per channel)
// ---------------------------------------------------------------------------
__global__ void prep_kernel(const float* __restrict__ pc,
                            const float* __restrict__ al) {
    int gid = blockIdx.x;            // 0 .. NG*NPTS-1
    int g = gid >> 11;               // / 2048
    int n = gid & 2047;
    int b = g >> 2, w = g & 3;
    int c = threadIdx.x;
    float x = pc[((size_t)(b << 11) + n) * DIM + c] * al[w * DIM + c];
    g_Xb[(size_t)gid * DIM + c] = x;
    float s = x * x;
    #pragma unroll
    for (int o = 16; o; o >>= 1) s += __shfl_xor_sync(0xffffffffu, s, o);
    __shared__ float red[4];
    if ((c & 31) == 0) red[c >> 5] = s;
    __syncthreads();
    if (c == 0) {
        g_diag[gid]   = red[0] + red[1] + red[2] + red[3];
        g_colsum[gid] = 0.f;
        g_v[0][gid]   = 1.0f / (float)NPTS;
    }
}

// ---------------------------------------------------------------------------
// Kernel 2: K = threshold(exp(-(di+dj-2*Xb Xb^T)/sigma)) for tj >= ti tiles,
// mirrored store for symmetry, fused column sums into g_colsum via atomics.
// grid = (NT*NT, NG), 256 threads, 128x128 tile, 8x8 per thread.
// ---------------------------------------------------------------------------
__global__ void __launch_bounds__(256) gram_kernel(const float* __restrict__ sigma) {
    int g  = blockIdx.y;
    int ti = blockIdx.x >> 4;
    int tj = blockIdx.x & 15;
    if (tj < ti) return;

    __shared__ float As[KC][TS + 4];
    __shared__ float Bs[KC][TS + 4];
    __shared__ float csum[TS], rsum[TS];

    int tid = threadIdx.x;
    int tx = tid & 15, ty = tid >> 4;

    float acc[8][8];
    #pragma unroll
    for (int r = 0; r < 8; r++)
        #pragma unroll
        for (int c = 0; c < 8; c++) acc[r][c] = 0.f;

    const float* Xg = g_Xb + (size_t)g * NPTS * DIM;

    for (int kc = 0; kc < DIM; kc += KC) {
        // load 128x16 tiles of A (rows ti*128..) and B (rows tj*128..)
        #pragma unroll
        for (int l = 0; l < 2; l++) {
            int fidx = tid * 2 + l;          // 0..511
            int row  = fidx >> 2;            // 0..127
            int k4   = (fidx & 3) << 2;      // 0,4,8,12
            float4 a = *(const float4*)&Xg[(size_t)(ti * TS + row) * DIM + kc + k4];
            As[k4 + 0][row] = a.x; As[k4 + 1][row] = a.y;
            As[k4 + 2][row] = a.z; As[k4 + 3][row] = a.w;
            float4 bb = *(const float4*)&Xg[(size_t)(tj * TS + row) * DIM + kc + k4];
            Bs[k4 + 0][row] = bb.x; Bs[k4 + 1][row] = bb.y;
            Bs[k4 + 2][row] = bb.z; Bs[k4 + 3][row] = bb.w;
        }
        __syncthreads();
        #pragma unroll
        for (int k = 0; k < KC; k++) {
            float4 a0 = *(const float4*)&As[k][ty * 4];
            float4 a1 = *(const float4*)&As[k][64 + ty * 4];
            float4 b0 = *(const float4*)&Bs[k][tx * 4];
            float4 b1 = *(const float4*)&Bs[k][64 + tx * 4];
            float ar[8] = {a0.x, a0.y, a0.z, a0.w, a1.x, a1.y, a1.z, a1.w};
            float bc[8] = {b0.x, b0.y, b0.z, b0.w, b1.x, b1.y, b1.z, b1.w};
            #pragma unroll
            for (int r = 0; r < 8; r++)
                #pragma unroll
                for (int c = 0; c < 8; c++)
                    acc[r][c] += ar[r] * bc[c];
        }
        __syncthreads();
    }

    float inv_sigma = 1.0f / *sigma;

    // local row/col indices: r<4 -> ty*4+r ; r>=4 -> 64+ty*4+(r-4)
    int rl[8], cl[8];
    #pragma unroll
    for (int r = 0; r < 8; r++) rl[r] = (r < 4) ? (ty * 4 + r) : (64 + ty * 4 + r - 4);
    #pragma unroll
    for (int c = 0; c < 8; c++) cl[c] = (c < 4) ? (tx * 4 + c) : (64 + tx * 4 + c - 4);

    float di[8], dj[8];
    #pragma unroll
    for (int r = 0; r < 8; r++) di[r] = g_diag[g * NPTS + ti * TS + rl[r]];
    #pragma unroll
    for (int c = 0; c < 8; c++) dj[c] = g_diag[g * NPTS + tj * TS + cl[c]];

    float kv[8][8];
    #pragma unroll
    for (int r = 0; r < 8; r++)
        #pragma unroll
        for (int c = 0; c < 8; c++) {
            float dd = di[r] + dj[c] - 2.0f * acc[r][c];
            float kk = __expf(-dd * inv_sigma);
            kv[r][c] = (kk < THRESH) ? 0.f : kk;
        }

    float* Kg = g_K + (size_t)g * NPTS * NPTS;
    // direct store: rows i (ti range), cols j (tj range)
    #pragma unroll
    for (int r = 0; r < 8; r++) {
        size_t base = (size_t)(ti * TS + rl[r]) * NPTS + tj * TS;
        float4 v0 = {kv[r][0], kv[r][1], kv[r][2], kv[r][3]};
        float4 v1 = {kv[r][4], kv[r][5], kv[r][6], kv[r][7]};
        *(float4*)&Kg[base + tx * 4]      = v0;
        *(float4*)&Kg[base + 64 + tx * 4] = v1;
    }
    // mirrored store (symmetry): K[j][i] = K[i][j]
    if (ti != tj) {
        #pragma unroll
        for (int c = 0; c < 8; c++) {
            size_t base = (size_t)(tj * TS + cl[c]) * NPTS + ti * TS;
            float4 v0 = {kv[0][c], kv[1][c], kv[2][c], kv[3][c]};
            float4 v1 = {kv[4][c], kv[5][c], kv[6][c], kv[7][c]};
            *(float4*)&Kg[base + ty * 4]      = v0;
            *(float4*)&Kg[base + 64 + ty * 4] = v1;
        }
    }

    // fused column sums: colsum[j] += sum_i K[i][j]
    if (tid < TS) { csum[tid] = 0.f; rsum[tid] = 0.f; }
    __syncthreads();
    #pragma unroll
    for (int c = 0; c < 8; c++) {
        float s = 0.f;
        #pragma unroll
        for (int r = 0; r < 8; r++) s += kv[r][c];
        atomicAdd(&csum[cl[c]], s);
    }
    if (ti != tj) {
        #pragma unroll
        for (int r = 0; r < 8; r++) {
            float s = 0.f;
            #pragma unroll
            for (int c = 0; c < 8; c++) s += kv[r][c];
            atomicAdd(&rsum[rl[r]], s);
        }
    }
    __syncthreads();
    if (tid < TS) {
        atomicAdd(&g_colsum[g * NPTS + tj * TS + tid], csum[tid]);
        if (ti != tj)
            atomicAdd(&g_colsum[g * NPTS + ti * TS + tid], rsum[tid]);
    }
}

// ---------------------------------------------------------------------------
// Kernel 3 (x8): v_{t+1}[j] = 0.5*(K v_t)[j]/colsum[j] + 0.5*v_t[j]
// one warp per row of K; pure HBM streaming.
// ---------------------------------------------------------------------------
__global__ void __launch_bounds__(256) step_kernel(int t) {
    int wid  = (blockIdx.x * blockDim.x + threadIdx.x) >> 5;
    int lane = threadIdx.x & 31;
    if (wid >= NG * NPTS) return;
    int g = wid >> 11;
    int j = wid & 2047;
    const float* Krow = &g_K[((size_t)g * NPTS + j) * NPTS];
    const float* v    = &g_v[t][g * NPTS];
    float acc = 0.f;
    #pragma unroll 4
    for (int i4 = lane * 4; i4 < NPTS; i4 += 32 * 4) {
        float4 kk = *(const float4*)&Krow[i4];
        float4 vv = *(const float4*)&v[i4];
        acc += kk.x * vv.x + kk.y * vv.y + kk.z * vv.z + kk.w * vv.w;
    }
    #pragma unroll
    for (int o = 16; o; o >>= 1) acc += __shfl_xor_sync(0xffffffffu, acc, o);
    if (lane == 0) {
        int idx = g * NPTS + j;
        g_v[t + 1][idx] = 0.5f * acc / g_colsum[idx] + 0.5f * g_v[t][idx];
    }
}

// ---------------------------------------------------------------------------
// Kernel 4: feats[g, t, c] = sum_n v_t[g,n] * Xb[g,n,c], t in {0,1,2,4,8}
// grid = NG, 640 threads (5 t-groups x 128 channels). Writes every output.
// ---------------------------------------------------------------------------
__global__ void __launch_bounds__(640) feats_kernel(float* __restrict__ out) {
    int g   = blockIdx.x;
    int tid = threadIdx.x;   // 0..639
    int t   = tid >> 7;      // 0..4
    int c   = tid & 127;

    __shared__ float vs[5][NPTS];
    for (int i = tid; i < 5 * NPTS; i += 640) {
        int tt = i >> 11;
        int n  = i & 2047;
        int tsrc = (tt < 3) ? tt : ((tt == 3) ? 4 : 8);
        vs[tt][n] = g_v[tsrc][g * NPTS + n];
    }
    __syncthreads();

    const float* X = g_Xb + (size_t)g * NPTS * DIM + c;
    float acc = 0.f;
    #pragma unroll 8
    for (int n = 0; n < NPTS; n++)
        acc += vs[t][n] * X[(size_t)n * DIM];

    out[g * 640 + (t << 7) + c] = acc;
}

// ---------------------------------------------------------------------------
extern "C" void kernel_launch(void* const* d_in, const int* in_sizes, int n_in,
                              void* d_out, int out_size) {
    const float* pc = (const float*)d_in[0];   // point_clouds [4,2048,128]
    const float* al = (const float*)d_in[1];   // alphas [4,128]
    const float* sg = (const float*)d_in[2];   // sigma scalar
    float* out = (float*)d_out;                // [4, 2560] fp32

    prep_kernel<<<NG * NPTS, DIM>>>(pc, al);

    dim3 ggrid(NT * NT, NG);
    gram_kernel<<<ggrid, 256>>>(sg);

    for (int t = 0; t < 8; t++)
        step_kernel<<<(NG * NPTS) / 8, 256>>>(t);

    feats_kernel<<<NG, 640>>>(out);
}

// round 3
// speedup vs baseline: 1.2010x; 1.2010x over previous
#include <cuda_runtime.h>
#include <cuda_fp16.h>
#include <cstdint>

// Problem constants (fixed shapes per reference)
#define NG   16      // B * n_w = 4*4 graphs
#define NPTS 2048
#define DIM  128
#define TS   128     // gram tile size
#define NT   (NPTS/TS)   // 16 tiles per side
#define KC   16      // k chunk
#define THRESH 1e-5f

// Scratch (static device globals; no allocations anywhere)
__device__ float  g_Xb[(size_t)NG*NPTS*DIM];          // 16.8 MB
__device__ float  g_diag[NG*NPTS];
__device__ float  g_colsum[NG*NPTS];
__device__ __half g_K[(size_t)NG*NPTS*NPTS];          // 128 MB (fp16)
__device__ float  g_v[9][NG*NPTS];

// ---------------------------------------------------------------------------
// f32x2 packed helpers (Blackwell sm_100+: 2-wide fp32 FMA, 2x pipe rate)
// ---------------------------------------------------------------------------
__device__ __forceinline__ unsigned long long pack_f2(float lo, float hi) {
    unsigned long long r;
    asm("mov.b64 %0, {%1, %2};" : "=l"(r) : "f"(lo), "f"(hi));
    return r;
}
__device__ __forceinline__ void unpack_f2(unsigned long long v, float& lo, float& hi) {
    asm("mov.b64 {%0, %1}, %2;" : "=f"(lo), "=f"(hi) : "l"(v));
}
__device__ __forceinline__ void fma_f2(unsigned long long& acc,
                                       unsigned long long a,
                                       unsigned long long b) {
    asm("fma.rn.f32x2 %0, %1, %2, %0;" : "+l"(acc) : "l"(a), "l"(b));
}
// pack 4 floats -> 4 halves (uint2)
__device__ __forceinline__ uint2 pack4h(float a, float b, float c, float d) {
    __half2 h0 = __floats2half2_rn(a, b);
    __half2 h1 = __floats2half2_rn(c, d);
    uint2 r;
    r.x = *reinterpret_cast<unsigned*>(&h0);
    r.y = *reinterpret_cast<unsigned*>(&h1);
    return r;
}

// ---------------------------------------------------------------------------
// Kernel 1: Xb = pc * alpha, diag = ||Xb_row||^2, zero colsum, v0 = 1/N
// ---------------------------------------------------------------------------
__global__ void prep_kernel(const float* __restrict__ pc,
                            const float* __restrict__ al) {
    int gid = blockIdx.x;            // 0 .. NG*NPTS-1
    int g = gid >> 11;
    int n = gid & 2047;
    int b = g >> 2, w = g & 3;
    int c = threadIdx.x;
    float x = pc[((size_t)(b << 11) + n) * DIM + c] * al[w * DIM + c];
    g_Xb[(size_t)gid * DIM + c] = x;
    float s = x * x;
    #pragma unroll
    for (int o = 16; o; o >>= 1) s += __shfl_xor_sync(0xffffffffu, s, o);
    __shared__ float red[4];
    if ((c & 31) == 0) red[c >> 5] = s;
    __syncthreads();
    if (c == 0) {
        g_diag[gid]   = red[0] + red[1] + red[2] + red[3];
        g_colsum[gid] = 0.f;
        g_v[0][gid]   = 1.0f / (float)NPTS;
    }
}

// ---------------------------------------------------------------------------
// Kernel 2: K = threshold(exp(-(di+dj-2*Xb Xb^T)/sigma)) for tj >= ti tiles,
// mirrored store (symmetry), fused column sums. Inner product in f32x2.
// ---------------------------------------------------------------------------
__global__ void __launch_bounds__(256) gram_kernel(const float* __restrict__ sigma) {
    int g  = blockIdx.y;
    int ti = blockIdx.x >> 4;
    int tj = blockIdx.x & 15;
    if (tj < ti) return;

    __shared__ float As[KC][TS + 4];
    __shared__ float Bs[KC][TS + 4];
    __shared__ float csum[TS], rsum[TS];

    int tid = threadIdx.x;
    int tx = tid & 15, ty = tid >> 4;

    // acc2[r][c2]: lanes (kv[r][2*c2], kv[r][2*c2+1])
    unsigned long long acc2[8][4];
    #pragma unroll
    for (int r = 0; r < 8; r++)
        #pragma unroll
        for (int c = 0; c < 4; c++) acc2[r][c] = 0ull;

    const float* Xg = g_Xb + (size_t)g * NPTS * DIM;

    for (int kc = 0; kc < DIM; kc += KC) {
        #pragma unroll
        for (int l = 0; l < 2; l++) {
            int fidx = tid * 2 + l;          // 0..511
            int row  = fidx >> 2;            // 0..127
            int k4   = (fidx & 3) << 2;      // 0,4,8,12
            float4 a = *(const float4*)&Xg[(size_t)(ti * TS + row) * DIM + kc + k4];
            As[k4 + 0][row] = a.x; As[k4 + 1][row] = a.y;
            As[k4 + 2][row] = a.z; As[k4 + 3][row] = a.w;
            float4 bb = *(const float4*)&Xg[(size_t)(tj * TS + row) * DIM + kc + k4];
            Bs[k4 + 0][row] = bb.x; Bs[k4 + 1][row] = bb.y;
            Bs[k4 + 2][row] = bb.z; Bs[k4 + 3][row] = bb.w;
        }
        __syncthreads();
        #pragma unroll
        for (int k = 0; k < KC; k++) {
            float4 a0 = *(const float4*)&As[k][ty * 4];
            float4 a1 = *(const float4*)&As[k][64 + ty * 4];
            float4 b0 = *(const float4*)&Bs[k][tx * 4];
            float4 b1 = *(const float4*)&Bs[k][64 + tx * 4];
            unsigned long long bc2[4];
            bc2[0] = pack_f2(b0.x, b0.y);
            bc2[1] = pack_f2(b0.z, b0.w);
            bc2[2] = pack_f2(b1.x, b1.y);
            bc2[3] = pack_f2(b1.z, b1.w);
            float ar[8] = {a0.x, a0.y, a0.z, a0.w, a1.x, a1.y, a1.z, a1.w};
            #pragma unroll
            for (int r = 0; r < 8; r++) {
                unsigned long long ar2 = pack_f2(ar[r], ar[r]);
                #pragma unroll
                for (int c = 0; c < 4; c++)
                    fma_f2(acc2[r][c], ar2, bc2[c]);
            }
        }
        __syncthreads();
    }

    float inv_sigma = 1.0f / *sigma;

    // local row/col indices: r<4 -> ty*4+r ; r>=4 -> 64+ty*4+(r-4)
    int rl[8], cl[8];
    #pragma unroll
    for (int r = 0; r < 8; r++) rl[r] = (r < 4) ? (ty * 4 + r) : (64 + ty * 4 + r - 4);
    #pragma unroll
    for (int c = 0; c < 8; c++) cl[c] = (c < 4) ? (tx * 4 + c) : (64 + tx * 4 + c - 4);

    float di[8], dj[8];
    #pragma unroll
    for (int r = 0; r < 8; r++) di[r] = g_diag[g * NPTS + ti * TS + rl[r]];
    #pragma unroll
    for (int c = 0; c < 8; c++) dj[c] = g_diag[g * NPTS + tj * TS + cl[c]];

    float kv[8][8];
    #pragma unroll
    for (int r = 0; r < 8; r++)
        #pragma unroll
        for (int c2 = 0; c2 < 4; c2++) {
            float lo, hi;
            unpack_f2(acc2[r][c2], lo, hi);
            {
                float dd = di[r] + dj[2 * c2] - 2.0f * lo;
                float kk = __expf(-dd * inv_sigma);
                kv[r][2 * c2] = (kk < THRESH) ? 0.f : kk;
            }
            {
                float dd = di[r] + dj[2 * c2 + 1] - 2.0f * hi;
                float kk = __expf(-dd * inv_sigma);
                kv[r][2 * c2 + 1] = (kk < THRESH) ? 0.f : kk;
            }
        }

    __half* Kg = g_K + (size_t)g * NPTS * NPTS;
    // direct store: rows i (ti range), cols j (tj range) — 8B vectorized halves
    #pragma unroll
    for (int r = 0; r < 8; r++) {
        size_t base = (size_t)(ti * TS + rl[r]) * NPTS + tj * TS;
        *(uint2*)&Kg[base + tx * 4]      = pack4h(kv[r][0], kv[r][1], kv[r][2], kv[r][3]);
        *(uint2*)&Kg[base + 64 + tx * 4] = pack4h(kv[r][4], kv[r][5], kv[r][6], kv[r][7]);
    }
    // mirrored store (symmetry): K[j][i] = K[i][j]
    if (ti != tj) {
        #pragma unroll
        for (int c = 0; c < 8; c++) {
            size_t base = (size_t)(tj * TS + cl[c]) * NPTS + ti * TS;
            *(uint2*)&Kg[base + ty * 4]      = pack4h(kv[0][c], kv[1][c], kv[2][c], kv[3][c]);
            *(uint2*)&Kg[base + 64 + ty * 4] = pack4h(kv[4][c], kv[5][c], kv[6][c], kv[7][c]);
        }
    }

    // fused column sums: colsum[j] += sum_i K[i][j]   (fp32 exact values)
    if (tid < TS) { csum[tid] = 0.f; rsum[tid] = 0.f; }
    __syncthreads();
    #pragma unroll
    for (int c = 0; c < 8; c++) {
        float s = 0.f;
        #pragma unroll
        for (int r = 0; r < 8; r++) s += kv[r][c];
        atomicAdd(&csum[cl[c]], s);
    }
    if (ti != tj) {
        #pragma unroll
        for (int r = 0; r < 8; r++) {
            float s = 0.f;
            #pragma unroll
            for (int c = 0; c < 8; c++) s += kv[r][c];
            atomicAdd(&rsum[rl[r]], s);
        }
    }
    __syncthreads();
    if (tid < TS) {
        atomicAdd(&g_colsum[g * NPTS + tj * TS + tid], csum[tid]);
        if (ti != tj)
            atomicAdd(&g_colsum[g * NPTS + ti * TS + tid], rsum[tid]);
    }
}

// ---------------------------------------------------------------------------
// Kernel 3 (x8): v_{t+1}[j] = 0.5*(K v_t)[j]/colsum[j] + 0.5*v_t[j]
// one warp per row of fp16 K; pure HBM/L2 streaming.
// ---------------------------------------------------------------------------
__global__ void __launch_bounds__(256) step_kernel(int t) {
    int wid  = (blockIdx.x * blockDim.x + threadIdx.x) >> 5;
    int lane = threadIdx.x & 31;
    if (wid >= NG * NPTS) return;
    int g = wid >> 11;
    int j = wid & 2047;
    const __half* Krow = &g_K[((size_t)g * NPTS + j) * NPTS];
    const float*  v    = &g_v[t][g * NPTS];
    float acc = 0.f;
    #pragma unroll
    for (int it = 0; it < 8; it++) {
        int i0 = it * 256 + lane * 8;           // 8 halves per lane per iter
        uint4 kk = *(const uint4*)&Krow[i0];
        float4 va = *(const float4*)&v[i0];
        float4 vb = *(const float4*)&v[i0 + 4];
        float2 f;
        f = __half22float2(*reinterpret_cast<__half2*>(&kk.x));
        acc += f.x * va.x + f.y * va.y;
        f = __half22float2(*reinterpret_cast<__half2*>(&kk.y));
        acc += f.x * va.z + f.y * va.w;
        f = __half22float2(*reinterpret_cast<__half2*>(&kk.z));
        acc += f.x * vb.x + f.y * vb.y;
        f = __half22float2(*reinterpret_cast<__half2*>(&kk.w));
        acc += f.x * vb.z + f.y * vb.w;
    }
    #pragma unroll
    for (int o = 16; o; o >>= 1) acc += __shfl_xor_sync(0xffffffffu, acc, o);
    if (lane == 0) {
        int idx = g * NPTS + j;
        g_v[t + 1][idx] = 0.5f * acc / g_colsum[idx] + 0.5f * g_v[t][idx];
    }
}

// ---------------------------------------------------------------------------
// Kernel 4: feats[g, t, c] = sum_n v_t[g,n] * Xb[g,n,c], t in {0,1,2,4,8}
// ---------------------------------------------------------------------------
__global__ void __launch_bounds__(640) feats_kernel(float* __restrict__ out) {
    int g   = blockIdx.x;
    int tid = threadIdx.x;   // 0..639
    int t   = tid >> 7;      // 0..4
    int c   = tid & 127;

    __shared__ float vs[5][NPTS];
    for (int i = tid; i < 5 * NPTS; i += 640) {
        int tt = i >> 11;
        int n  = i & 2047;
        int tsrc = (tt < 3) ? tt : ((tt == 3) ? 4 : 8);
        vs[tt][n] = g_v[tsrc][g * NPTS + n];
    }
    __syncthreads();

    const float* X = g_Xb + (size_t)g * NPTS * DIM + c;
    float acc = 0.f;
    #pragma unroll 8
    for (int n = 0; n < NPTS; n++)
        acc += vs[t][n] * X[(size_t)n * DIM];

    out[g * 640 + (t << 7) + c] = acc;
}

// ---------------------------------------------------------------------------
extern "C" void kernel_launch(void* const* d_in, const int* in_sizes, int n_in,
                              void* d_out, int out_size) {
    const float* pc = (const float*)d_in[0];   // point_clouds [4,2048,128]
    const float* al = (const float*)d_in[1];   // alphas [4,128]
    const float* sg = (const float*)d_in[2];   // sigma scalar
    float* out = (float*)d_out;                // [4, 2560] fp32

    prep_kernel<<<NG * NPTS, DIM>>>(pc, al);

    dim3 ggrid(NT * NT, NG);
    gram_kernel<<<ggrid, 256>>>(sg);

    for (int t = 0; t < 8; t++)
        step_kernel<<<(NG * NPTS) / 8, 256>>>(t);

    feats_kernel<<<NG, 640>>>(out);
}

// round 5
// speedup vs baseline: 1.7435x; 1.4517x over previous
#include <cuda_runtime.h>
#include <cuda_fp16.h>
#include <cstdint>

#define NG   16
#define NPTS 2048
#define DIM  128
#define THRESH 1e-5f
#define LDA  136    // smem row stride in halves (padded: conflict-free ldmatrix)

// Scratch (static device globals; no allocations anywhere)
__device__ float  g_Xb[(size_t)NG*NPTS*DIM];          // fp32 Xb (feats)
__device__ __half g_Xh[(size_t)NG*NPTS*DIM];          // fp16 Xb (MMA)
__device__ float  g_diag[NG*NPTS];
__device__ float  g_colsum[NG*NPTS];
__device__ __half g_K[(size_t)NG*NPTS*NPTS];          // 128 MB fp16
__device__ float  g_v[9][NG*NPTS];
__device__ __half g_vh[9][NG*NPTS];

// ---------------------------------------------------------------------------
// helpers (baseline PTX only: ldmatrix sm_75+, mma.sync sm_80+)
// ---------------------------------------------------------------------------
__device__ __forceinline__ uint32_t smem_u32(const void* p) {
    return (uint32_t)__cvta_generic_to_shared(p);
}
__device__ __forceinline__ void ldm_x4(uint32_t* r, uint32_t addr) {
    asm volatile("ldmatrix.sync.aligned.m8n8.x4.shared.b16 {%0,%1,%2,%3}, [%4];"
                 : "=r"(r[0]), "=r"(r[1]), "=r"(r[2]), "=r"(r[3]) : "r"(addr));
}
__device__ __forceinline__ void mma16816(float* c, const uint32_t* a,
                                         uint32_t b0, uint32_t b1) {
    asm volatile(
        "mma.sync.aligned.m16n8k16.row.col.f32.f16.f16.f32 "
        "{%0,%1,%2,%3}, {%4,%5,%6,%7}, {%8,%9}, {%0,%1,%2,%3};"
        : "+f"(c[0]), "+f"(c[1]), "+f"(c[2]), "+f"(c[3])
        : "r"(a[0]), "r"(a[1]), "r"(a[2]), "r"(a[3]), "r"(b0), "r"(b1));
}

// ---------------------------------------------------------------------------
// Kernel 1: Xb = pc*alpha (fp32 + fp16), diag, zero colsum, v0
// ---------------------------------------------------------------------------
__global__ void prep_kernel(const float* __restrict__ pc,
                            const float* __restrict__ al) {
    int gid = blockIdx.x;
    int g = gid >> 11;
    int n = gid & 2047;
    int b = g >> 2, w = g & 3;
    int c = threadIdx.x;
    float x = pc[((size_t)(b << 11) + n) * DIM + c] * al[w * DIM + c];
    g_Xb[(size_t)gid * DIM + c] = x;
    g_Xh[(size_t)gid * DIM + c] = __float2half_rn(x);
    float s = x * x;
    #pragma unroll
    for (int o = 16; o; o >>= 1) s += __shfl_xor_sync(0xffffffffu, s, o);
    __shared__ float red[4];
    if ((c & 31) == 0) red[c >> 5] = s;
    __syncthreads();
    if (c == 0) {
        g_diag[gid]   = red[0] + red[1] + red[2] + red[3];
        g_colsum[gid] = 0.f;
        float v0 = 1.0f / (float)NPTS;
        g_v[0][gid]  = v0;
        g_vh[0][gid] = __float2half_rn(v0);
    }
}

// ---------------------------------------------------------------------------
// Kernel 2: HMMA Gram + exp epilogue + fused rowsum(=colsum by symmetry).
// One CTA per (g, ti, tj): 128x128 output, K=128 in one shot.
// 256 threads = 8 warps, warp tile 64(m) x 32(n), m16n8k16 fragments.
// Dynamic SMEM: A tile + B tile, 128 x 136 halves each.
// ---------------------------------------------------------------------------
#define GRAM_SMEM (2 * 128 * LDA * 2)

__global__ void __launch_bounds__(256) gram_mma_kernel(const float* __restrict__ sigma) {
    extern __shared__ __half smem[];
    __shared__ float dj_s[128];
    __shared__ float csum[128];

    int tid = threadIdx.x, wid = tid >> 5, lane = tid & 31;
    int g  = blockIdx.y;
    int ti = blockIdx.x >> 4;
    int tj = blockIdx.x & 15;
    int warp_m = wid & 1;    // 0..1 (64 m-rows each)
    int warp_n = wid >> 1;   // 0..3 (32 n-cols each)

    __half* sA = smem;
    __half* sB = smem + 128 * LDA;

    const __half* XA = g_Xh + ((size_t)g * NPTS + ti * 128) * DIM;
    const __half* XB = g_Xh + ((size_t)g * NPTS + tj * 128) * DIM;
    #pragma unroll
    for (int l = 0; l < 8; l++) {
        int ch  = tid + l * 256;     // 0..2047 8-half chunks
        int row = ch >> 4;
        int c8  = (ch & 15) << 3;
        *(uint4*)&sA[row * LDA + c8] = *(const uint4*)&XA[(size_t)row * DIM + c8];
        *(uint4*)&sB[row * LDA + c8] = *(const uint4*)&XB[(size_t)row * DIM + c8];
    }
    if (tid < 128) {
        dj_s[tid] = g_diag[g * NPTS + tj * 128 + tid];
        csum[tid] = 0.f;
    }
    __syncthreads();

    // per-thread ldmatrix base addresses (x4 ordering: t&15 -> row, t>>4 -> col8)
    uint32_t aBase = smem_u32(sA) +
        (((warp_m * 64 + (lane & 15)) * LDA + ((lane >> 4) << 3)) << 1);
    uint32_t bBase = smem_u32(sB) +
        (((warp_n * 32 + (lane & 15)) * LDA + ((lane >> 4) << 3)) << 1);

    float acc[4][4][4];
    #pragma unroll
    for (int mi = 0; mi < 4; mi++)
        #pragma unroll
        for (int ni = 0; ni < 4; ni++)
            #pragma unroll
            for (int e = 0; e < 4; e++) acc[mi][ni][e] = 0.f;

    #pragma unroll
    for (int ks = 0; ks < 8; ks++) {
        uint32_t Af[4][4], Bf[2][4];
        #pragma unroll
        for (int mi = 0; mi < 4; mi++)
            ldm_x4(Af[mi], aBase + ((mi * 16 * LDA + ks * 16) << 1));
        #pragma unroll
        for (int nj = 0; nj < 2; nj++)
            ldm_x4(Bf[nj], bBase + ((nj * 16 * LDA + ks * 16) << 1));
        #pragma unroll
        for (int mi = 0; mi < 4; mi++)
            #pragma unroll
            for (int ni = 0; ni < 4; ni++)
                mma16816(acc[mi][ni], Af[mi],
                         Bf[ni >> 1][ni & 1], Bf[ni >> 1][2 + (ni & 1)]);
    }

    // Epilogue
    float inv_s = 1.0f / *sigma;
    int r = lane >> 2, q = lane & 3;
    __half* Kg = g_K + (size_t)g * NPTS * NPTS;

    #pragma unroll
    for (int mi = 0; mi < 4; mi++) {
        int lr0 = warp_m * 64 + mi * 16 + r;       // local rows lr0, lr0+8
        float di0 = g_diag[g * NPTS + ti * 128 + lr0];
        float di1 = g_diag[g * NPTS + ti * 128 + lr0 + 8];
        float rs0 = 0.f, rs1 = 0.f;
        #pragma unroll
        for (int ni = 0; ni < 4; ni++) {
            int lc = warp_n * 32 + ni * 8 + q * 2;
            float dj0 = dj_s[lc], dj1 = dj_s[lc + 1];
            float* a = acc[mi][ni];
            float k00 = __expf(-(di0 + dj0 - 2.0f * a[0]) * inv_s);
            float k01 = __expf(-(di0 + dj1 - 2.0f * a[1]) * inv_s);
            float k10 = __expf(-(di1 + dj0 - 2.0f * a[2]) * inv_s);
            float k11 = __expf(-(di1 + dj1 - 2.0f * a[3]) * inv_s);
            k00 = (k00 < THRESH) ? 0.f : k00;
            k01 = (k01 < THRESH) ? 0.f : k01;
            k10 = (k10 < THRESH) ? 0.f : k10;
            k11 = (k11 < THRESH) ? 0.f : k11;
            rs0 += k00 + k01;
            rs1 += k10 + k11;
            __half2 h0 = __floats2half2_rn(k00, k01);
            __half2 h1 = __floats2half2_rn(k10, k11);
            size_t c0 = (size_t)(ti * 128 + lr0) * NPTS + tj * 128 + lc;
            size_t c1 = (size_t)(ti * 128 + lr0 + 8) * NPTS + tj * 128 + lc;
            *(__half2*)&Kg[c0] = h0;
            *(__half2*)&Kg[c1] = h1;
        }
        // quad reduce (lanes sharing same row)
        rs0 += __shfl_xor_sync(0xffffffffu, rs0, 1);
        rs0 += __shfl_xor_sync(0xffffffffu, rs0, 2);
        rs1 += __shfl_xor_sync(0xffffffffu, rs1, 1);
        rs1 += __shfl_xor_sync(0xffffffffu, rs1, 2);
        if (q == 0) {
            atomicAdd(&csum[lr0], rs0);
            atomicAdd(&csum[lr0 + 8], rs1);
        }
    }
    __syncthreads();
    // colsum[j] == rowsum[j] by symmetry of K
    if (tid < 128)
        atomicAdd(&g_colsum[g * NPTS + ti * 128 + tid], csum[tid]);
}

// ---------------------------------------------------------------------------
// Kernel 3 (x8): v_{t+1}[j] = 0.5*(K v_t)[j]/colsum[j] + 0.5*v_t[j]
// 2 rows per warp (shared v loads, 2x MLP); fp16 K + fp16 v, fp32 chunk acc.
// ---------------------------------------------------------------------------
__global__ void __launch_bounds__(256) step_kernel(int t) {
    int wid  = (blockIdx.x * blockDim.x + threadIdx.x) >> 5;   // 0..16383
    int lane = threadIdx.x & 31;
    int g  = wid >> 10;
    int j0 = wid & 1023;        // rows j0 and j0+1024
    const __half* KrA = &g_K[((size_t)g * NPTS + j0) * NPTS];
    const __half* KrB = &g_K[((size_t)g * NPTS + j0 + 1024) * NPTS];
    const __half* vh  = &g_vh[t][g * NPTS];
    float accA = 0.f, accB = 0.f;
    #pragma unroll
    for (int it = 0; it < 8; it++) {
        int i0 = it * 256 + lane * 8;
        uint4 vv = *(const uint4*)&vh[i0];
        uint4 ka = *(const uint4*)&KrA[i0];
        uint4 kb = *(const uint4*)&KrB[i0];
        __half2 ha = __hmul2(*(__half2*)&ka.x, *(__half2*)&vv.x);
        ha = __hfma2(*(__half2*)&ka.y, *(__half2*)&vv.y, ha);
        ha = __hfma2(*(__half2*)&ka.z, *(__half2*)&vv.z, ha);
        ha = __hfma2(*(__half2*)&ka.w, *(__half2*)&vv.w, ha);
        __half2 hb = __hmul2(*(__half2*)&kb.x, *(__half2*)&vv.x);
        hb = __hfma2(*(__half2*)&kb.y, *(__half2*)&vv.y, hb);
        hb = __hfma2(*(__half2*)&kb.z, *(__half2*)&vv.z, hb);
        hb = __hfma2(*(__half2*)&kb.w, *(__half2*)&vv.w, hb);
        float2 fa = __half22float2(ha);
        float2 fb = __half22float2(hb);
        accA += fa.x + fa.y;
        accB += fb.x + fb.y;
    }
    #pragma unroll
    for (int o = 16; o; o >>= 1) {
        accA += __shfl_xor_sync(0xffffffffu, accA, o);
        accB += __shfl_xor_sync(0xffffffffu, accB, o);
    }
    if (lane == 0) {
        int ia = g * NPTS + j0;
        int ib = ia + 1024;
        float na = 0.5f * accA / g_colsum[ia] + 0.5f * g_v[t][ia];
        float nb = 0.5f * accB / g_colsum[ib] + 0.5f * g_v[t][ib];
        g_v[t + 1][ia]  = na;
        g_v[t + 1][ib]  = nb;
        g_vh[t + 1][ia] = __float2half_rn(na);
        g_vh[t + 1][ib] = __float2half_rn(nb);
    }
}

// ---------------------------------------------------------------------------
// Kernel 4: feats[g, t, c] = sum_n v_t[g,n] * Xb[g,n,c], t in {0,1,2,4,8}
// ---------------------------------------------------------------------------
__global__ void __launch_bounds__(640) feats_kernel(float* __restrict__ out) {
    int g   = blockIdx.x;
    int tid = threadIdx.x;
    int t   = tid >> 7;
    int c   = tid & 127;

    __shared__ float vs[5][NPTS];
    for (int i = tid; i < 5 * NPTS; i += 640) {
        int tt = i >> 11;
        int n  = i & 2047;
        int tsrc = (tt < 3) ? tt : ((tt == 3) ? 4 : 8);
        vs[tt][n] = g_v[tsrc][g * NPTS + n];
    }
    __syncthreads();

    const float* X = g_Xb + (size_t)g * NPTS * DIM + c;
    float acc = 0.f;
    #pragma unroll 8
    for (int n = 0; n < NPTS; n++)
        acc += vs[t][n] * X[(size_t)n * DIM];

    out[g * 640 + (t << 7) + c] = acc;
}

// ---------------------------------------------------------------------------
extern "C" void kernel_launch(void* const* d_in, const int* in_sizes, int n_in,
                              void* d_out, int out_size) {
    const float* pc = (const float*)d_in[0];   // point_clouds [4,2048,128]
    const float* al = (const float*)d_in[1];   // alphas [4,128]
    const float* sg = (const float*)d_in[2];   // sigma scalar
    float* out = (float*)d_out;                // [4, 2560] fp32

    cudaFuncSetAttribute(gram_mma_kernel,
                         cudaFuncAttributeMaxDynamicSharedMemorySize, GRAM_SMEM);

    prep_kernel<<<NG * NPTS, DIM>>>(pc, al);

    dim3 ggrid(256, NG);   // all 16x16 tile pairs
    gram_mma_kernel<<<ggrid, 256, GRAM_SMEM>>>(sg);

    for (int t = 0; t < 8; t++)
        step_kernel<<<2048, 256>>>(t);

    feats_kernel<<<NG, 640>>>(out);
}

// round 6
// speedup vs baseline: 1.8041x; 1.0348x over previous
#include <cuda_runtime.h>
#include <cuda_fp16.h>
#include <cstdint>

#define NG   16
#define NPTS 2048
#define DIM  128
#define THRESH 1e-5f
#define LDA  136    // smem row stride in halves (padded: conflict-free ldmatrix)

// Scratch (static device globals; no allocations anywhere)
__device__ float  g_Xb[(size_t)NG*NPTS*DIM];          // fp32 Xb (feats)
__device__ __half g_Xh[(size_t)NG*NPTS*DIM];          // fp16 Xb (MMA)
__device__ float  g_diag[NG*NPTS];
__device__ float  g_colsum[NG*NPTS];
__device__ __half g_K[(size_t)NG*NPTS*NPTS];          // 128 MB fp16
__device__ float  g_v[9][NG*NPTS];
__device__ __half g_vh[9][NG*NPTS];

// ---------------------------------------------------------------------------
// helpers (baseline PTX only: ldmatrix/movmatrix sm_75+, mma.sync sm_80+)
// ---------------------------------------------------------------------------
__device__ __forceinline__ uint32_t smem_u32(const void* p) {
    return (uint32_t)__cvta_generic_to_shared(p);
}
__device__ __forceinline__ void ldm_x4(uint32_t* r, uint32_t addr) {
    asm volatile("ldmatrix.sync.aligned.m8n8.x4.shared.b16 {%0,%1,%2,%3}, [%4];"
                 : "=r"(r[0]), "=r"(r[1]), "=r"(r[2]), "=r"(r[3]) : "r"(addr));
}
__device__ __forceinline__ void mma16816(float* c, const uint32_t* a,
                                         uint32_t b0, uint32_t b1) {
    asm volatile(
        "mma.sync.aligned.m16n8k16.row.col.f32.f16.f16.f32 "
        "{%0,%1,%2,%3}, {%4,%5,%6,%7}, {%8,%9}, {%0,%1,%2,%3};"
        : "+f"(c[0]), "+f"(c[1]), "+f"(c[2]), "+f"(c[3])
        : "r"(a[0]), "r"(a[1]), "r"(a[2]), "r"(a[3]), "r"(b0), "r"(b1));
}
__device__ __forceinline__ uint32_t movm_trans(uint32_t x) {
    uint32_t d;
    asm volatile("movmatrix.sync.aligned.m8n8.trans.b16 %0, %1;" : "=r"(d) : "r"(x));
    return d;
}

// ---------------------------------------------------------------------------
// Kernel 1: Xb = pc*alpha (fp32 + fp16), diag, zero colsum, v0
// ---------------------------------------------------------------------------
__global__ void prep_kernel(const float* __restrict__ pc,
                            const float* __restrict__ al) {
    int gid = blockIdx.x;
    int g = gid >> 11;
    int n = gid & 2047;
    int b = g >> 2, w = g & 3;
    int c = threadIdx.x;
    float x = pc[((size_t)(b << 11) + n) * DIM + c] * al[w * DIM + c];
    g_Xb[(size_t)gid * DIM + c] = x;
    g_Xh[(size_t)gid * DIM + c] = __float2half_rn(x);
    float s = x * x;
    #pragma unroll
    for (int o = 16; o; o >>= 1) s += __shfl_xor_sync(0xffffffffu, s, o);
    __shared__ float red[4];
    if ((c & 31) == 0) red[c >> 5] = s;
    __syncthreads();
    if (c == 0) {
        g_diag[gid]   = red[0] + red[1] + red[2] + red[3];
        g_colsum[gid] = 0.f;
        float v0 = 1.0f / (float)NPTS;
        g_v[0][gid]  = v0;
        g_vh[0][gid] = __float2half_rn(v0);
    }
}

// ---------------------------------------------------------------------------
// Kernel 2: HMMA Gram, SYMMETRIC: only tile pairs tj >= ti (136 per graph).
// exp epilogue; mirror tile written via movmatrix transpose; fused row/col
// sums feed colsum for both blocks.
// 256 threads = 8 warps, warp tile 64(m) x 32(n), m16n8k16 fragments.
// ---------------------------------------------------------------------------
#define GRAM_SMEM (2 * 128 * LDA * 2)

__global__ void __launch_bounds__(256) gram_mma_kernel(const float* __restrict__ sigma) {
    extern __shared__ __half smem[];
    __shared__ float dj_s[128];
    __shared__ float rs_s[128];   // tile row sums  -> colsum[ti block]
    __shared__ float cs_s[128];   // tile col sums  -> colsum[tj block]

    int tid = threadIdx.x, wid = tid >> 5, lane = tid & 31;
    int g = blockIdx.y;

    // decode upper-triangular pair (ti <= tj) from blockIdx.x in [0,136)
    int idx = blockIdx.x, ti = 0;
    while (idx >= 16 - ti) { idx -= 16 - ti; ti++; }
    int tj = ti + idx;

    int warp_m = wid & 1;    // 0..1 (64 m-rows each)
    int warp_n = wid >> 1;   // 0..3 (32 n-cols each)

    __half* sA = smem;
    __half* sB = smem + 128 * LDA;

    const __half* XA = g_Xh + ((size_t)g * NPTS + ti * 128) * DIM;
    const __half* XB = g_Xh + ((size_t)g * NPTS + tj * 128) * DIM;
    #pragma unroll
    for (int l = 0; l < 8; l++) {
        int ch  = tid + l * 256;     // 0..2047 8-half chunks
        int row = ch >> 4;
        int c8  = (ch & 15) << 3;
        *(uint4*)&sA[row * LDA + c8] = *(const uint4*)&XA[(size_t)row * DIM + c8];
        *(uint4*)&sB[row * LDA + c8] = *(const uint4*)&XB[(size_t)row * DIM + c8];
    }
    if (tid < 128) {
        dj_s[tid] = g_diag[g * NPTS + tj * 128 + tid];
        rs_s[tid] = 0.f;
        cs_s[tid] = 0.f;
    }
    __syncthreads();

    uint32_t aBase = smem_u32(sA) +
        (((warp_m * 64 + (lane & 15)) * LDA + ((lane >> 4) << 3)) << 1);
    uint32_t bBase = smem_u32(sB) +
        (((warp_n * 32 + (lane & 15)) * LDA + ((lane >> 4) << 3)) << 1);

    float acc[4][4][4];
    #pragma unroll
    for (int mi = 0; mi < 4; mi++)
        #pragma unroll
        for (int ni = 0; ni < 4; ni++)
            #pragma unroll
            for (int e = 0; e < 4; e++) acc[mi][ni][e] = 0.f;

    #pragma unroll
    for (int ks = 0; ks < 8; ks++) {
        uint32_t Af[4][4], Bf[2][4];
        #pragma unroll
        for (int mi = 0; mi < 4; mi++)
            ldm_x4(Af[mi], aBase + ((mi * 16 * LDA + ks * 16) << 1));
        #pragma unroll
        for (int nj = 0; nj < 2; nj++)
            ldm_x4(Bf[nj], bBase + ((nj * 16 * LDA + ks * 16) << 1));
        #pragma unroll
        for (int mi = 0; mi < 4; mi++)
            #pragma unroll
            for (int ni = 0; ni < 4; ni++)
                mma16816(acc[mi][ni], Af[mi],
                         Bf[ni >> 1][ni & 1], Bf[ni >> 1][2 + (ni & 1)]);
    }

    // Epilogue: exp / threshold / half2 pack + row & col sums
    float inv_s = 1.0f / *sigma;
    int r = lane >> 2, q = lane & 3;
    uint32_t h_up[4][4], h_lo[4][4];
    float csA[4] = {0.f, 0.f, 0.f, 0.f};   // col 2q per ni
    float csB[4] = {0.f, 0.f, 0.f, 0.f};   // col 2q+1 per ni

    #pragma unroll
    for (int mi = 0; mi < 4; mi++) {
        int lr0 = warp_m * 64 + mi * 16 + r;       // local rows lr0, lr0+8
        float di0 = g_diag[g * NPTS + ti * 128 + lr0];
        float di1 = g_diag[g * NPTS + ti * 128 + lr0 + 8];
        float rs0 = 0.f, rs1 = 0.f;
        #pragma unroll
        for (int ni = 0; ni < 4; ni++) {
            int lc = warp_n * 32 + ni * 8 + q * 2;
            float dj0 = dj_s[lc], dj1 = dj_s[lc + 1];
            float* a = acc[mi][ni];
            float k00 = __expf(-(di0 + dj0 - 2.0f * a[0]) * inv_s);
            float k01 = __expf(-(di0 + dj1 - 2.0f * a[1]) * inv_s);
            float k10 = __expf(-(di1 + dj0 - 2.0f * a[2]) * inv_s);
            float k11 = __expf(-(di1 + dj1 - 2.0f * a[3]) * inv_s);
            k00 = (k00 < THRESH) ? 0.f : k00;
            k01 = (k01 < THRESH) ? 0.f : k01;
            k10 = (k10 < THRESH) ? 0.f : k10;
            k11 = (k11 < THRESH) ? 0.f : k11;
            rs0 += k00 + k01;
            rs1 += k10 + k11;
            csA[ni] += k00 + k10;
            csB[ni] += k01 + k11;
            __half2 h0 = __floats2half2_rn(k00, k01);
            __half2 h1 = __floats2half2_rn(k10, k11);
            h_up[mi][ni] = *reinterpret_cast<uint32_t*>(&h0);
            h_lo[mi][ni] = *reinterpret_cast<uint32_t*>(&h1);
        }
        rs0 += __shfl_xor_sync(0xffffffffu, rs0, 1);
        rs0 += __shfl_xor_sync(0xffffffffu, rs0, 2);
        rs1 += __shfl_xor_sync(0xffffffffu, rs1, 1);
        rs1 += __shfl_xor_sync(0xffffffffu, rs1, 2);
        if (q == 0) {
            atomicAdd(&rs_s[lr0], rs0);
            atomicAdd(&rs_s[lr0 + 8], rs1);
        }
    }
    // column sums: reduce over r (lanes differing in bits 2..4)
    #pragma unroll
    for (int ni = 0; ni < 4; ni++) {
        float a = csA[ni], b = csB[ni];
        #pragma unroll
        for (int o = 4; o <= 16; o <<= 1) {
            a += __shfl_xor_sync(0xffffffffu, a, o);
            b += __shfl_xor_sync(0xffffffffu, b, o);
        }
        if (r == 0) {
            atomicAdd(&cs_s[warp_n * 32 + ni * 8 + 2 * q], a);
            atomicAdd(&cs_s[warp_n * 32 + ni * 8 + 2 * q + 1], b);
        }
    }

    __half* Kg = g_K + (size_t)g * NPTS * NPTS;
    // direct store: K[ti block][tj block]
    #pragma unroll
    for (int mi = 0; mi < 4; mi++) {
        int lr0 = warp_m * 64 + mi * 16 + r;
        #pragma unroll
        for (int ni = 0; ni < 4; ni++) {
            int lc = warp_n * 32 + ni * 8 + q * 2;
            size_t c0 = (size_t)(ti * 128 + lr0) * NPTS + tj * 128 + lc;
            *(uint32_t*)&Kg[c0]            = h_up[mi][ni];
            *(uint32_t*)&Kg[c0 + 8 * (size_t)NPTS] = h_lo[mi][ni];
        }
    }
    // mirror store: K[tj block][ti block] = tile^T via movmatrix
    if (ti != tj) {
        #pragma unroll
        for (int mi = 0; mi < 4; mi++) {
            int row0 = warp_m * 64 + mi * 16;
            #pragma unroll
            for (int ni = 0; ni < 4; ni++) {
                int col0 = warp_n * 32 + ni * 8;
                uint32_t tu = movm_trans(h_up[mi][ni]);
                uint32_t tl = movm_trans(h_lo[mi][ni]);
                size_t a0 = (size_t)(tj * 128 + col0 + r) * NPTS + ti * 128 + row0 + 2 * q;
                *(uint32_t*)&Kg[a0]     = tu;
                *(uint32_t*)&Kg[a0 + 8] = tl;
            }
        }
    }

    __syncthreads();
    if (tid < 128) {
        // mirror tile contributes rowsums to colsum[ti block];
        // direct tile contributes colsums to colsum[tj block].
        // diagonal tile (ti==tj): counted once via rowsums (tile symmetric).
        atomicAdd(&g_colsum[g * NPTS + ti * 128 + tid], rs_s[tid]);
        if (ti != tj)
            atomicAdd(&g_colsum[g * NPTS + tj * 128 + tid], cs_s[tid]);
    }
}

// ---------------------------------------------------------------------------
// Kernel 3 (x8): v_{t+1}[j] = 0.5*(K v_t)[j]/colsum[j] + 0.5*v_t[j]
// 4 rows per warp (shared v loads, 4x MLP); fp16 K + fp16 v, fp32 chunk acc.
// ---------------------------------------------------------------------------
__global__ void __launch_bounds__(256) step_kernel(int t) {
    int wid  = (blockIdx.x * blockDim.x + threadIdx.x) >> 5;   // 0..8191
    int lane = threadIdx.x & 31;
    int g  = wid >> 9;
    int j0 = wid & 511;         // rows j0 + {0,512,1024,1536}
    const __half* Kr0 = &g_K[((size_t)g * NPTS + j0) * NPTS];
    const __half* Kr1 = Kr0 + (size_t)512 * NPTS;
    const __half* Kr2 = Kr0 + (size_t)1024 * NPTS;
    const __half* Kr3 = Kr0 + (size_t)1536 * NPTS;
    const __half* vh  = &g_vh[t][g * NPTS];
    float a0 = 0.f, a1 = 0.f, a2 = 0.f, a3 = 0.f;
    #pragma unroll
    for (int it = 0; it < 8; it++) {
        int i0 = it * 256 + lane * 8;
        uint4 vv = *(const uint4*)&vh[i0];
        uint4 k0 = *(const uint4*)&Kr0[i0];
        uint4 k1 = *(const uint4*)&Kr1[i0];
        uint4 k2 = *(const uint4*)&Kr2[i0];
        uint4 k3 = *(const uint4*)&Kr3[i0];
        __half2 h0 = __hmul2(*(__half2*)&k0.x, *(__half2*)&vv.x);
        __half2 h1 = __hmul2(*(__half2*)&k1.x, *(__half2*)&vv.x);
        __half2 h2 = __hmul2(*(__half2*)&k2.x, *(__half2*)&vv.x);
        __half2 h3 = __hmul2(*(__half2*)&k3.x, *(__half2*)&vv.x);
        h0 = __hfma2(*(__half2*)&k0.y, *(__half2*)&vv.y, h0);
        h1 = __hfma2(*(__half2*)&k1.y, *(__half2*)&vv.y, h1);
        h2 = __hfma2(*(__half2*)&k2.y, *(__half2*)&vv.y, h2);
        h3 = __hfma2(*(__half2*)&k3.y, *(__half2*)&vv.y, h3);
        h0 = __hfma2(*(__half2*)&k0.z, *(__half2*)&vv.z, h0);
        h1 = __hfma2(*(__half2*)&k1.z, *(__half2*)&vv.z, h1);
        h2 = __hfma2(*(__half2*)&k2.z, *(__half2*)&vv.z, h2);
        h3 = __hfma2(*(__half2*)&k3.z, *(__half2*)&vv.z, h3);
        h0 = __hfma2(*(__half2*)&k0.w, *(__half2*)&vv.w, h0);
        h1 = __hfma2(*(__half2*)&k1.w, *(__half2*)&vv.w, h1);
        h2 = __hfma2(*(__half2*)&k2.w, *(__half2*)&vv.w, h2);
        h3 = __hfma2(*(__half2*)&k3.w, *(__half2*)&vv.w, h3);
        float2 f0 = __half22float2(h0);
        float2 f1 = __half22float2(h1);
        float2 f2 = __half22float2(h2);
        float2 f3 = __half22float2(h3);
        a0 += f0.x + f0.y;
        a1 += f1.x + f1.y;
        a2 += f2.x + f2.y;
        a3 += f3.x + f3.y;
    }
    #pragma unroll
    for (int o = 16; o; o >>= 1) {
        a0 += __shfl_xor_sync(0xffffffffu, a0, o);
        a1 += __shfl_xor_sync(0xffffffffu, a1, o);
        a2 += __shfl_xor_sync(0xffffffffu, a2, o);
        a3 += __shfl_xor_sync(0xffffffffu, a3, o);
    }
    if (lane == 0) {
        int base = g * NPTS + j0;
        float acc[4] = {a0, a1, a2, a3};
        #pragma unroll
        for (int s = 0; s < 4; s++) {
            int ix = base + s * 512;
            float nv = 0.5f * acc[s] / g_colsum[ix] + 0.5f * g_v[t][ix];
            g_v[t + 1][ix]  = nv;
            g_vh[t + 1][ix] = __float2half_rn(nv);
        }
    }
}

// ---------------------------------------------------------------------------
// Kernel 4: feats[g, t, c] = sum_n v_t[g,n] * Xb[g,n,c], t in {0,1,2,4,8}
// ---------------------------------------------------------------------------
__global__ void __launch_bounds__(640) feats_kernel(float* __restrict__ out) {
    int g   = blockIdx.x;
    int tid = threadIdx.x;
    int t   = tid >> 7;
    int c   = tid & 127;

    __shared__ float vs[5][NPTS];
    for (int i = tid; i < 5 * NPTS; i += 640) {
        int tt = i >> 11;
        int n  = i & 2047;
        int tsrc = (tt < 3) ? tt : ((tt == 3) ? 4 : 8);
        vs[tt][n] = g_v[tsrc][g * NPTS + n];
    }
    __syncthreads();

    const float* X = g_Xb + (size_t)g * NPTS * DIM + c;
    float acc = 0.f;
    #pragma unroll 8
    for (int n = 0; n < NPTS; n++)
        acc += vs[t][n] * X[(size_t)n * DIM];

    out[g * 640 + (t << 7) + c] = acc;
}

// ---------------------------------------------------------------------------
extern "C" void kernel_launch(void* const* d_in, const int* in_sizes, int n_in,
                              void* d_out, int out_size) {
    const float* pc = (const float*)d_in[0];   // point_clouds [4,2048,128]
    const float* al = (const float*)d_in[1];   // alphas [4,128]
    const float* sg = (const float*)d_in[2];   // sigma scalar
    float* out = (float*)d_out;                // [4, 2560] fp32

    cudaFuncSetAttribute(gram_mma_kernel,
                         cudaFuncAttributeMaxDynamicSharedMemorySize, GRAM_SMEM);

    prep_kernel<<<NG * NPTS, DIM>>>(pc, al);

    dim3 ggrid(136, NG);   // upper-triangular tile pairs
    gram_mma_kernel<<<ggrid, 256, GRAM_SMEM>>>(sg);

    for (int t = 0; t < 8; t++)
        step_kernel<<<1024, 256>>>(t);

    feats_kernel<<<NG, 640>>>(out);
}

// round 7
// speedup vs baseline: 2.2847x; 1.2663x over previous
#include <cuda_runtime.h>
#include <cuda_fp16.h>
#include <cstdint>

#define NG   16
#define NPTS 2048
#define DIM  128
#define THRESH 1e-5f
#define LDA  136    // smem row stride in halves

// Scratch (static device globals; no allocations anywhere)
__device__ float  g_Xb[(size_t)NG*NPTS*DIM];          // fp32 Xb (feats)
__device__ __half g_Xh[(size_t)NG*NPTS*DIM];          // fp16 Xb (MMA)
__device__ float  g_diag[NG*NPTS];
__device__ float  g_colsum[NG*NPTS];
__device__ __half g_K[(size_t)NG*NPTS*NPTS];          // upper tiles only used
__device__ float  g_v[9][NG*NPTS];
__device__ __half g_vh[9][NG*NPTS];
__device__ float  g_y[NG*NPTS];                        // step accumulator

// ---------------------------------------------------------------------------
// helpers (baseline PTX only)
// ---------------------------------------------------------------------------
__device__ __forceinline__ uint32_t smem_u32(const void* p) {
    return (uint32_t)__cvta_generic_to_shared(p);
}
__device__ __forceinline__ void ldm_x4(uint32_t* r, uint32_t addr) {
    asm volatile("ldmatrix.sync.aligned.m8n8.x4.shared.b16 {%0,%1,%2,%3}, [%4];"
                 : "=r"(r[0]), "=r"(r[1]), "=r"(r[2]), "=r"(r[3]) : "r"(addr));
}
__device__ __forceinline__ void mma16816(float* c, const uint32_t* a,
                                         uint32_t b0, uint32_t b1) {
    asm volatile(
        "mma.sync.aligned.m16n8k16.row.col.f32.f16.f16.f32 "
        "{%0,%1,%2,%3}, {%4,%5,%6,%7}, {%8,%9}, {%0,%1,%2,%3};"
        : "+f"(c[0]), "+f"(c[1]), "+f"(c[2]), "+f"(c[3])
        : "r"(a[0]), "r"(a[1]), "r"(a[2]), "r"(a[3]), "r"(b0), "r"(b1));
}

// ---------------------------------------------------------------------------
// Kernel 1: Xb = pc*alpha (fp32 + fp16), diag, zero colsum + y, v0
// ---------------------------------------------------------------------------
__global__ void prep_kernel(const float* __restrict__ pc,
                            const float* __restrict__ al) {
    int gid = blockIdx.x;
    int g = gid >> 11;
    int n = gid & 2047;
    int b = g >> 2, w = g & 3;
    int c = threadIdx.x;
    float x = pc[((size_t)(b << 11) + n) * DIM + c] * al[w * DIM + c];
    g_Xb[(size_t)gid * DIM + c] = x;
    g_Xh[(size_t)gid * DIM + c] = __float2half_rn(x);
    float s = x * x;
    #pragma unroll
    for (int o = 16; o; o >>= 1) s += __shfl_xor_sync(0xffffffffu, s, o);
    __shared__ float red[4];
    if ((c & 31) == 0) red[c >> 5] = s;
    __syncthreads();
    if (c == 0) {
        g_diag[gid]   = red[0] + red[1] + red[2] + red[3];
        g_colsum[gid] = 0.f;
        g_y[gid]      = 0.f;
        float v0 = 1.0f / (float)NPTS;
        g_v[0][gid]  = v0;
        g_vh[0][gid] = __float2half_rn(v0);
    }
}

// ---------------------------------------------------------------------------
// Kernel 2: HMMA Gram, upper-triangular tile pairs only (136 per graph).
// exp epilogue, fused row/col sums -> colsum. NO mirror store (steps read
// only upper tiles and apply symmetry themselves).
// ---------------------------------------------------------------------------
#define GRAM_SMEM (2 * 128 * LDA * 2)

__global__ void __launch_bounds__(256) gram_mma_kernel(const float* __restrict__ sigma) {
    extern __shared__ __half smem[];
    __shared__ float dj_s[128];
    __shared__ float rs_s[128];   // tile row sums  -> colsum[ti block]
    __shared__ float cs_s[128];   // tile col sums  -> colsum[tj block]

    int tid = threadIdx.x, wid = tid >> 5, lane = tid & 31;
    int g = blockIdx.y;

    int idx = blockIdx.x, ti = 0;
    while (idx >= 16 - ti) { idx -= 16 - ti; ti++; }
    int tj = ti + idx;

    int warp_m = wid & 1;
    int warp_n = wid >> 1;

    __half* sA = smem;
    __half* sB = smem + 128 * LDA;

    const __half* XA = g_Xh + ((size_t)g * NPTS + ti * 128) * DIM;
    const __half* XB = g_Xh + ((size_t)g * NPTS + tj * 128) * DIM;
    #pragma unroll
    for (int l = 0; l < 8; l++) {
        int ch  = tid + l * 256;
        int row = ch >> 4;
        int c8  = (ch & 15) << 3;
        *(uint4*)&sA[row * LDA + c8] = *(const uint4*)&XA[(size_t)row * DIM + c8];
        *(uint4*)&sB[row * LDA + c8] = *(const uint4*)&XB[(size_t)row * DIM + c8];
    }
    if (tid < 128) {
        dj_s[tid] = g_diag[g * NPTS + tj * 128 + tid];
        rs_s[tid] = 0.f;
        cs_s[tid] = 0.f;
    }
    __syncthreads();

    uint32_t aBase = smem_u32(sA) +
        (((warp_m * 64 + (lane & 15)) * LDA + ((lane >> 4) << 3)) << 1);
    uint32_t bBase = smem_u32(sB) +
        (((warp_n * 32 + (lane & 15)) * LDA + ((lane >> 4) << 3)) << 1);

    float acc[4][4][4];
    #pragma unroll
    for (int mi = 0; mi < 4; mi++)
        #pragma unroll
        for (int ni = 0; ni < 4; ni++)
            #pragma unroll
            for (int e = 0; e < 4; e++) acc[mi][ni][e] = 0.f;

    #pragma unroll
    for (int ks = 0; ks < 8; ks++) {
        uint32_t Af[4][4], Bf[2][4];
        #pragma unroll
        for (int mi = 0; mi < 4; mi++)
            ldm_x4(Af[mi], aBase + ((mi * 16 * LDA + ks * 16) << 1));
        #pragma unroll
        for (int nj = 0; nj < 2; nj++)
            ldm_x4(Bf[nj], bBase + ((nj * 16 * LDA + ks * 16) << 1));
        #pragma unroll
        for (int mi = 0; mi < 4; mi++)
            #pragma unroll
            for (int ni = 0; ni < 4; ni++)
                mma16816(acc[mi][ni], Af[mi],
                         Bf[ni >> 1][ni & 1], Bf[ni >> 1][2 + (ni & 1)]);
    }

    float inv_s = 1.0f / *sigma;
    int r = lane >> 2, q = lane & 3;
    uint32_t h_up[4][4], h_lo[4][4];
    float csA[4] = {0.f, 0.f, 0.f, 0.f};
    float csB[4] = {0.f, 0.f, 0.f, 0.f};

    #pragma unroll
    for (int mi = 0; mi < 4; mi++) {
        int lr0 = warp_m * 64 + mi * 16 + r;
        float di0 = g_diag[g * NPTS + ti * 128 + lr0];
        float di1 = g_diag[g * NPTS + ti * 128 + lr0 + 8];
        float rs0 = 0.f, rs1 = 0.f;
        #pragma unroll
        for (int ni = 0; ni < 4; ni++) {
            int lc = warp_n * 32 + ni * 8 + q * 2;
            float dj0 = dj_s[lc], dj1 = dj_s[lc + 1];
            float* a = acc[mi][ni];
            float k00 = __expf(-(di0 + dj0 - 2.0f * a[0]) * inv_s);
            float k01 = __expf(-(di0 + dj1 - 2.0f * a[1]) * inv_s);
            float k10 = __expf(-(di1 + dj0 - 2.0f * a[2]) * inv_s);
            float k11 = __expf(-(di1 + dj1 - 2.0f * a[3]) * inv_s);
            k00 = (k00 < THRESH) ? 0.f : k00;
            k01 = (k01 < THRESH) ? 0.f : k01;
            k10 = (k10 < THRESH) ? 0.f : k10;
            k11 = (k11 < THRESH) ? 0.f : k11;
            rs0 += k00 + k01;
            rs1 += k10 + k11;
            csA[ni] += k00 + k10;
            csB[ni] += k01 + k11;
            __half2 h0 = __floats2half2_rn(k00, k01);
            __half2 h1 = __floats2half2_rn(k10, k11);
            h_up[mi][ni] = *reinterpret_cast<uint32_t*>(&h0);
            h_lo[mi][ni] = *reinterpret_cast<uint32_t*>(&h1);
        }
        rs0 += __shfl_xor_sync(0xffffffffu, rs0, 1);
        rs0 += __shfl_xor_sync(0xffffffffu, rs0, 2);
        rs1 += __shfl_xor_sync(0xffffffffu, rs1, 1);
        rs1 += __shfl_xor_sync(0xffffffffu, rs1, 2);
        if (q == 0) {
            atomicAdd(&rs_s[lr0], rs0);
            atomicAdd(&rs_s[lr0 + 8], rs1);
        }
    }
    #pragma unroll
    for (int ni = 0; ni < 4; ni++) {
        float a = csA[ni], b = csB[ni];
        #pragma unroll
        for (int o = 4; o <= 16; o <<= 1) {
            a += __shfl_xor_sync(0xffffffffu, a, o);
            b += __shfl_xor_sync(0xffffffffu, b, o);
        }
        if (r == 0) {
            atomicAdd(&cs_s[warp_n * 32 + ni * 8 + 2 * q], a);
            atomicAdd(&cs_s[warp_n * 32 + ni * 8 + 2 * q + 1], b);
        }
    }

    __half* Kg = g_K + (size_t)g * NPTS * NPTS;
    #pragma unroll
    for (int mi = 0; mi < 4; mi++) {
        int lr0 = warp_m * 64 + mi * 16 + r;
        #pragma unroll
        for (int ni = 0; ni < 4; ni++) {
            int lc = warp_n * 32 + ni * 8 + q * 2;
            size_t c0 = (size_t)(ti * 128 + lr0) * NPTS + tj * 128 + lc;
            *(uint32_t*)&Kg[c0]                    = h_up[mi][ni];
            *(uint32_t*)&Kg[c0 + 8 * (size_t)NPTS] = h_lo[mi][ni];
        }
    }

    __syncthreads();
    if (tid < 128) {
        atomicAdd(&g_colsum[g * NPTS + ti * 128 + tid], rs_s[tid]);
        if (ti != tj)
            atomicAdd(&g_colsum[g * NPTS + tj * 128 + tid], cs_s[tid]);
    }
}

// ---------------------------------------------------------------------------
// Kernel 3a (x8): symmetric tiled mat-vec. CTA per upper tile (ti,tj):
//   y[ti-block] += T  * v[tj-block]   (fused into coalesced tile load)
//   y[tj-block] += T^T* v[ti-block]   (smem pass, conflict-free)
// ---------------------------------------------------------------------------
__global__ void __launch_bounds__(256) step_tile_kernel(int t) {
    __shared__ __half tile[128 * LDA];      // 34816 B
    __shared__ __half vti_h[128];
    __shared__ float2 cpart[256];

    int tid = threadIdx.x;
    int g = blockIdx.y;
    int idx = blockIdx.x, ti = 0;
    while (idx >= 16 - ti) { idx -= 16 - ti; ti++; }
    int tj = ti + idx;
    bool offdiag = (ti != tj);

    if (tid < 128)
        vti_h[tid] = g_vh[t][g * NPTS + ti * 128 + tid];

    // this thread's fixed 8-column chunk of vtj (cols (tid&15)*8 ..+7)
    int c16 = tid & 15;
    uint4 vvr = *(const uint4*)&g_vh[t][g * NPTS + tj * 128 + c16 * 8];
    const __half2* vj2 = (const __half2*)&vvr;

    const __half* Kt = g_K + ((size_t)g * NPTS + ti * 128) * NPTS + tj * 128;
    float racc[8];

    // load tile (coalesced) + fused row dots
    #pragma unroll
    for (int l = 0; l < 8; l++) {
        int ch  = tid + l * 256;
        int row = ch >> 4;                 // (tid>>4) + 16*l
        uint4 kk = *(const uint4*)&Kt[(size_t)row * NPTS + c16 * 8];
        if (offdiag)
            *(uint4*)&tile[row * LDA + c16 * 8] = kk;
        const __half2* k2 = (const __half2*)&kk;
        __half2 s = __hmul2(k2[0], vj2[0]);
        s = __hfma2(k2[1], vj2[1], s);
        s = __hfma2(k2[2], vj2[2], s);
        s = __hfma2(k2[3], vj2[3], s);
        float2 f = __half22float2(s);
        racc[l] = f.x + f.y;
    }
    // reduce each row over its 16 lanes (lanes 0-15 / 16-31 are separate rows)
    #pragma unroll
    for (int l = 0; l < 8; l++) {
        float a = racc[l];
        #pragma unroll
        for (int o = 1; o < 16; o <<= 1) a += __shfl_xor_sync(0xffffffffu, a, o);
        if ((tid & 15) == 0) {
            int row = (tid >> 4) + 16 * l;
            atomicAdd(&g_y[g * NPTS + ti * 128 + row], a);
        }
    }

    if (!offdiag) return;
    __syncthreads();

    // transpose pass: y[tj*128 + col] += sum_i T[i][col] * vti[i]
    // thread: colpair cp = tid&63 (cols 2cp,2cp+1), row quarter rh = tid>>6
    int cp = tid & 63;
    int rh = tid >> 6;
    float2 ca = {0.f, 0.f};
    #pragma unroll
    for (int ib = 0; ib < 32; ib += 8) {
        __half2 s = {__float2half(0.f), __float2half(0.f)};
        #pragma unroll
        for (int i = 0; i < 8; i++) {
            int ri = rh * 32 + ib + i;
            __half2 k = *(const __half2*)&tile[ri * LDA + cp * 2];
            s = __hfma2(k, __half2half2(vti_h[ri]), s);
        }
        float2 f = __half22float2(s);
        ca.x += f.x;
        ca.y += f.y;
    }
    cpart[tid] = ca;
    __syncthreads();
    if (tid < 64) {
        float2 a = cpart[tid], b = cpart[tid + 64];
        float2 c = cpart[tid + 128], d = cpart[tid + 192];
        float s0 = a.x + b.x + c.x + d.x;
        float s1 = a.y + b.y + c.y + d.y;
        atomicAdd(&g_y[g * NPTS + tj * 128 + 2 * tid], s0);
        atomicAdd(&g_y[g * NPTS + tj * 128 + 2 * tid + 1], s1);
    }
}

// ---------------------------------------------------------------------------
// Kernel 3b (x8): v_{t+1} = 0.5*y/colsum + 0.5*v_t ; reset y.
// ---------------------------------------------------------------------------
__global__ void finalize_kernel(int t) {
    int i = blockIdx.x * 256 + threadIdx.x;    // NG*NPTS = 32768
    float y = g_y[i];
    g_y[i] = 0.f;
    float nv = 0.5f * y / g_colsum[i] + 0.5f * g_v[t][i];
    g_v[t + 1][i]  = nv;
    g_vh[t + 1][i] = __float2half_rn(nv);
}

// ---------------------------------------------------------------------------
// Kernel 4: feats[g, t, c] = sum_n v_t[g,n] * Xb[g,n,c], t in {0,1,2,4,8}
// ---------------------------------------------------------------------------
__global__ void __launch_bounds__(640) feats_kernel(float* __restrict__ out) {
    int g   = blockIdx.x;
    int tid = threadIdx.x;
    int t   = tid >> 7;
    int c   = tid & 127;

    __shared__ float vs[5][NPTS];
    for (int i = tid; i < 5 * NPTS; i += 640) {
        int tt = i >> 11;
        int n  = i & 2047;
        int tsrc = (tt < 3) ? tt : ((tt == 3) ? 4 : 8);
        vs[tt][n] = g_v[tsrc][g * NPTS + n];
    }
    __syncthreads();

    const float* X = g_Xb + (size_t)g * NPTS * DIM + c;
    float acc = 0.f;
    #pragma unroll 8
    for (int n = 0; n < NPTS; n++)
        acc += vs[t][n] * X[(size_t)n * DIM];

    out[g * 640 + (t << 7) + c] = acc;
}

// ---------------------------------------------------------------------------
extern "C" void kernel_launch(void* const* d_in, const int* in_sizes, int n_in,
                              void* d_out, int out_size) {
    const float* pc = (const float*)d_in[0];   // point_clouds [4,2048,128]
    const float* al = (const float*)d_in[1];   // alphas [4,128]
    const float* sg = (const float*)d_in[2];   // sigma scalar
    float* out = (float*)d_out;                // [4, 2560] fp32

    cudaFuncSetAttribute(gram_mma_kernel,
                         cudaFuncAttributeMaxDynamicSharedMemorySize, GRAM_SMEM);

    prep_kernel<<<NG * NPTS, DIM>>>(pc, al);

    dim3 ggrid(136, NG);
    gram_mma_kernel<<<ggrid, 256, GRAM_SMEM>>>(sg);

    dim3 sgrid(136, NG);
    for (int t = 0; t < 8; t++) {
        step_tile_kernel<<<sgrid, 256>>>(t);
        finalize_kernel<<<128, 256>>>(t);
    }

    feats_kernel<<<NG, 640>>>(out);
}

// round 8
// speedup vs baseline: 3.7680x; 1.6493x over previous
#include <cuda_runtime.h>
#include <cuda_fp16.h>
#include <cstdint>

#define NG   16
#define NPTS 2048
#define DIM  128
#define THRESH 1e-5f
#define LDA  136    // smem row stride in halves

// Scratch (static device globals; no allocations anywhere)
__device__ float  g_Xb[(size_t)NG*NPTS*DIM];          // fp32 Xb
__device__ __half g_Xh[(size_t)NG*NPTS*DIM];          // fp16 Xb (MMA)
__device__ float  g_diag[NG*NPTS];
__device__ float  g_colsum[NG*NPTS];
__device__ __half g_K[(size_t)NG*NPTS*NPTS];          // upper tiles only
__device__ float  g_v[9][NG*NPTS];                    // v_1..v_7 used (+v_8 via y)
__device__ float  g_y[9][NG*NPTS];                    // y_1..y_8 accumulators
__device__ float  g_part[NG*16*5*DIM*2];              // feats partials (1.3 MB)

// ---------------------------------------------------------------------------
// helpers (baseline PTX only)
// ---------------------------------------------------------------------------
__device__ __forceinline__ uint32_t smem_u32(const void* p) {
    return (uint32_t)__cvta_generic_to_shared(p);
}
__device__ __forceinline__ void ldm_x4(uint32_t* r, uint32_t addr) {
    asm volatile("ldmatrix.sync.aligned.m8n8.x4.shared.b16 {%0,%1,%2,%3}, [%4];"
                 : "=r"(r[0]), "=r"(r[1]), "=r"(r[2]), "=r"(r[3]) : "r"(addr));
}
__device__ __forceinline__ void mma16816(float* c, const uint32_t* a,
                                         uint32_t b0, uint32_t b1) {
    asm volatile(
        "mma.sync.aligned.m16n8k16.row.col.f32.f16.f16.f32 "
        "{%0,%1,%2,%3}, {%4,%5,%6,%7}, {%8,%9}, {%0,%1,%2,%3};"
        : "+f"(c[0]), "+f"(c[1]), "+f"(c[2]), "+f"(c[3])
        : "r"(a[0]), "r"(a[1]), "r"(a[2]), "r"(a[3]), "r"(b0), "r"(b1));
}

// ---------------------------------------------------------------------------
// Kernel 1: Xb = pc*alpha (fp32 + fp16), diag, zero colsum + y buffers
// ---------------------------------------------------------------------------
__global__ void prep_kernel(const float* __restrict__ pc,
                            const float* __restrict__ al) {
    int gid = blockIdx.x;
    int g = gid >> 11;
    int n = gid & 2047;
    int b = g >> 2, w = g & 3;
    int c = threadIdx.x;
    float x = pc[((size_t)(b << 11) + n) * DIM + c] * al[w * DIM + c];
    g_Xb[(size_t)gid * DIM + c] = x;
    g_Xh[(size_t)gid * DIM + c] = __float2half_rn(x);
    float s = x * x;
    #pragma unroll
    for (int o = 16; o; o >>= 1) s += __shfl_xor_sync(0xffffffffu, s, o);
    __shared__ float red[4];
    if ((c & 31) == 0) red[c >> 5] = s;
    __syncthreads();
    if (c == 0) {
        g_diag[gid]   = red[0] + red[1] + red[2] + red[3];
        g_colsum[gid] = 0.f;
    }
    if (c >= 1 && c <= 8) g_y[c][gid] = 0.f;
}

// ---------------------------------------------------------------------------
// Kernel 2: HMMA Gram, upper-triangular tile pairs only (136 per graph).
// exp epilogue, fused row/col sums -> colsum. Upper tiles stored only.
// ---------------------------------------------------------------------------
#define GRAM_SMEM (2 * 128 * LDA * 2)

__global__ void __launch_bounds__(256) gram_mma_kernel(const float* __restrict__ sigma) {
    extern __shared__ __half smem[];
    __shared__ float dj_s[128];
    __shared__ float rs_s[128];
    __shared__ float cs_s[128];

    int tid = threadIdx.x, wid = tid >> 5, lane = tid & 31;
    int g = blockIdx.y;

    int idx = blockIdx.x, ti = 0;
    while (idx >= 16 - ti) { idx -= 16 - ti; ti++; }
    int tj = ti + idx;

    int warp_m = wid & 1;
    int warp_n = wid >> 1;

    __half* sA = smem;
    __half* sB = smem + 128 * LDA;

    const __half* XA = g_Xh + ((size_t)g * NPTS + ti * 128) * DIM;
    const __half* XB = g_Xh + ((size_t)g * NPTS + tj * 128) * DIM;
    #pragma unroll
    for (int l = 0; l < 8; l++) {
        int ch  = tid + l * 256;
        int row = ch >> 4;
        int c8  = (ch & 15) << 3;
        *(uint4*)&sA[row * LDA + c8] = *(const uint4*)&XA[(size_t)row * DIM + c8];
        *(uint4*)&sB[row * LDA + c8] = *(const uint4*)&XB[(size_t)row * DIM + c8];
    }
    if (tid < 128) {
        dj_s[tid] = g_diag[g * NPTS + tj * 128 + tid];
        rs_s[tid] = 0.f;
        cs_s[tid] = 0.f;
    }
    __syncthreads();

    uint32_t aBase = smem_u32(sA) +
        (((warp_m * 64 + (lane & 15)) * LDA + ((lane >> 4) << 3)) << 1);
    uint32_t bBase = smem_u32(sB) +
        (((warp_n * 32 + (lane & 15)) * LDA + ((lane >> 4) << 3)) << 1);

    float acc[4][4][4];
    #pragma unroll
    for (int mi = 0; mi < 4; mi++)
        #pragma unroll
        for (int ni = 0; ni < 4; ni++)
            #pragma unroll
            for (int e = 0; e < 4; e++) acc[mi][ni][e] = 0.f;

    #pragma unroll
    for (int ks = 0; ks < 8; ks++) {
        uint32_t Af[4][4], Bf[2][4];
        #pragma unroll
        for (int mi = 0; mi < 4; mi++)
            ldm_x4(Af[mi], aBase + ((mi * 16 * LDA + ks * 16) << 1));
        #pragma unroll
        for (int nj = 0; nj < 2; nj++)
            ldm_x4(Bf[nj], bBase + ((nj * 16 * LDA + ks * 16) << 1));
        #pragma unroll
        for (int mi = 0; mi < 4; mi++)
            #pragma unroll
            for (int ni = 0; ni < 4; ni++)
                mma16816(acc[mi][ni], Af[mi],
                         Bf[ni >> 1][ni & 1], Bf[ni >> 1][2 + (ni & 1)]);
    }

    float inv_s = 1.0f / *sigma;
    int r = lane >> 2, q = lane & 3;
    uint32_t h_up[4][4], h_lo[4][4];
    float csA[4] = {0.f, 0.f, 0.f, 0.f};
    float csB[4] = {0.f, 0.f, 0.f, 0.f};

    #pragma unroll
    for (int mi = 0; mi < 4; mi++) {
        int lr0 = warp_m * 64 + mi * 16 + r;
        float di0 = g_diag[g * NPTS + ti * 128 + lr0];
        float di1 = g_diag[g * NPTS + ti * 128 + lr0 + 8];
        float rs0 = 0.f, rs1 = 0.f;
        #pragma unroll
        for (int ni = 0; ni < 4; ni++) {
            int lc = warp_n * 32 + ni * 8 + q * 2;
            float dj0 = dj_s[lc], dj1 = dj_s[lc + 1];
            float* a = acc[mi][ni];
            float k00 = __expf(-(di0 + dj0 - 2.0f * a[0]) * inv_s);
            float k01 = __expf(-(di0 + dj1 - 2.0f * a[1]) * inv_s);
            float k10 = __expf(-(di1 + dj0 - 2.0f * a[2]) * inv_s);
            float k11 = __expf(-(di1 + dj1 - 2.0f * a[3]) * inv_s);
            k00 = (k00 < THRESH) ? 0.f : k00;
            k01 = (k01 < THRESH) ? 0.f : k01;
            k10 = (k10 < THRESH) ? 0.f : k10;
            k11 = (k11 < THRESH) ? 0.f : k11;
            rs0 += k00 + k01;
            rs1 += k10 + k11;
            csA[ni] += k00 + k10;
            csB[ni] += k01 + k11;
            __half2 h0 = __floats2half2_rn(k00, k01);
            __half2 h1 = __floats2half2_rn(k10, k11);
            h_up[mi][ni] = *reinterpret_cast<uint32_t*>(&h0);
            h_lo[mi][ni] = *reinterpret_cast<uint32_t*>(&h1);
        }
        rs0 += __shfl_xor_sync(0xffffffffu, rs0, 1);
        rs0 += __shfl_xor_sync(0xffffffffu, rs0, 2);
        rs1 += __shfl_xor_sync(0xffffffffu, rs1, 1);
        rs1 += __shfl_xor_sync(0xffffffffu, rs1, 2);
        if (q == 0) {
            atomicAdd(&rs_s[lr0], rs0);
            atomicAdd(&rs_s[lr0 + 8], rs1);
        }
    }
    #pragma unroll
    for (int ni = 0; ni < 4; ni++) {
        float a = csA[ni], b = csB[ni];
        #pragma unroll
        for (int o = 4; o <= 16; o <<= 1) {
            a += __shfl_xor_sync(0xffffffffu, a, o);
            b += __shfl_xor_sync(0xffffffffu, b, o);
        }
        if (r == 0) {
            atomicAdd(&cs_s[warp_n * 32 + ni * 8 + 2 * q], a);
            atomicAdd(&cs_s[warp_n * 32 + ni * 8 + 2 * q + 1], b);
        }
    }

    __half* Kg = g_K + (size_t)g * NPTS * NPTS;
    #pragma unroll
    for (int mi = 0; mi < 4; mi++) {
        int lr0 = warp_m * 64 + mi * 16 + r;
        #pragma unroll
        for (int ni = 0; ni < 4; ni++) {
            int lc = warp_n * 32 + ni * 8 + q * 2;
            size_t c0 = (size_t)(ti * 128 + lr0) * NPTS + tj * 128 + lc;
            *(uint32_t*)&Kg[c0]                    = h_up[mi][ni];
            *(uint32_t*)&Kg[c0 + 8 * (size_t)NPTS] = h_lo[mi][ni];
        }
    }

    __syncthreads();
    if (tid < 128) {
        atomicAdd(&g_colsum[g * NPTS + ti * 128 + tid], rs_s[tid]);
        if (ti != tj)
            atomicAdd(&g_colsum[g * NPTS + tj * 128 + tid], cs_s[tid]);
    }
}

// ---------------------------------------------------------------------------
// Kernel 3 (x8): fused normalize + symmetric tiled mat-vec.
// Step s: v_s = 0.5*y_s/colsum + 0.5*v_{s-1} (computed per-CTA, written
// redundantly with identical bits), then y_{s+1} += K v_s using upper tiles:
//   y[ti] += T * v[tj]   (fused into coalesced tile load)
//   y[tj] += T^T * v[ti] (smem pass)
// ---------------------------------------------------------------------------
__global__ void __launch_bounds__(256) step_tile_kernel(int s) {
    __shared__ __half tile[128 * LDA];
    __shared__ __half vti_h[128];
    __shared__ __half vtj_h[128];
    __shared__ float2 cpart[256];

    int tid = threadIdx.x;
    int g = blockIdx.y;
    int idx = blockIdx.x, ti = 0;
    while (idx >= 16 - ti) { idx -= 16 - ti; ti++; }
    int tj = ti + idx;
    bool offdiag = (ti != tj);

    int base_ti = g * NPTS + ti * 128;
    int base_tj = g * NPTS + tj * 128;

    if (s == 0) {
        __half h0 = __float2half_rn(1.0f / (float)NPTS);   // exact in fp16
        if (tid < 128) vti_h[tid] = h0;
        else           vtj_h[tid - 128] = h0;
    } else {
        if (tid < 128) {
            int ix = base_ti + tid;
            float vprev = (s == 1) ? (1.0f / (float)NPTS) : g_v[s - 1][ix];
            float nv = 0.5f * g_y[s][ix] / g_colsum[ix] + 0.5f * vprev;
            g_v[s][ix] = nv;                     // redundant identical writes
            vti_h[tid] = __float2half_rn(nv);
        } else {
            int ix = base_tj + (tid - 128);
            float vprev = (s == 1) ? (1.0f / (float)NPTS) : g_v[s - 1][ix];
            float nv = 0.5f * g_y[s][ix] / g_colsum[ix] + 0.5f * vprev;
            g_v[s][ix] = nv;
            vtj_h[tid - 128] = __float2half_rn(nv);
        }
    }
    __syncthreads();

    int c16 = tid & 15;
    uint4 vvr = *(const uint4*)&vtj_h[c16 * 8];
    const __half2* vj2 = (const __half2*)&vvr;

    const __half* Kt = g_K + ((size_t)g * NPTS + ti * 128) * NPTS + tj * 128;
    float racc[8];

    #pragma unroll
    for (int l = 0; l < 8; l++) {
        int ch  = tid + l * 256;
        int row = ch >> 4;
        uint4 kk = *(const uint4*)&Kt[(size_t)row * NPTS + c16 * 8];
        if (offdiag)
            *(uint4*)&tile[row * LDA + c16 * 8] = kk;
        const __half2* k2 = (const __half2*)&kk;
        __half2 ss = __hmul2(k2[0], vj2[0]);
        ss = __hfma2(k2[1], vj2[1], ss);
        ss = __hfma2(k2[2], vj2[2], ss);
        ss = __hfma2(k2[3], vj2[3], ss);
        float2 f = __half22float2(ss);
        racc[l] = f.x + f.y;
    }
    #pragma unroll
    for (int l = 0; l < 8; l++) {
        float a = racc[l];
        #pragma unroll
        for (int o = 1; o < 16; o <<= 1) a += __shfl_xor_sync(0xffffffffu, a, o);
        if ((tid & 15) == 0) {
            int row = (tid >> 4) + 16 * l;
            atomicAdd(&g_y[s + 1][base_ti + row], a);
        }
    }

    if (!offdiag) return;
    __syncthreads();

    int cp = tid & 63;
    int rh = tid >> 6;
    float2 ca = {0.f, 0.f};
    #pragma unroll
    for (int ib = 0; ib < 32; ib += 8) {
        __half2 ss = {__float2half(0.f), __float2half(0.f)};
        #pragma unroll
        for (int i = 0; i < 8; i++) {
            int ri = rh * 32 + ib + i;
            __half2 k = *(const __half2*)&tile[ri * LDA + cp * 2];
            ss = __hfma2(k, __half2half2(vti_h[ri]), ss);
        }
        float2 f = __half22float2(ss);
        ca.x += f.x;
        ca.y += f.y;
    }
    cpart[tid] = ca;
    __syncthreads();
    if (tid < 64) {
        float2 a = cpart[tid], b = cpart[tid + 64];
        float2 c = cpart[tid + 128], d = cpart[tid + 192];
        atomicAdd(&g_y[s + 1][base_tj + 2 * tid],     a.x + b.x + c.x + d.x);
        atomicAdd(&g_y[s + 1][base_tj + 2 * tid + 1], a.y + b.y + c.y + d.y);
    }
}

// ---------------------------------------------------------------------------
// Kernel 4a: coalesced feats partials. CTA per (chunk, g), 256 threads.
// Computes v_8 inline (finalize of y_8). Writes per-chunk partial dots.
// ---------------------------------------------------------------------------
__global__ void __launch_bounds__(256) feats_part_kernel() {
    __shared__ float vs[5][128];
    int chunk = blockIdx.x, g = blockIdx.y;
    int tid = threadIdx.x;

    if (tid < 128) {
        int ix = g * NPTS + chunk * 128 + tid;
        vs[0][tid] = 1.0f / (float)NPTS;
        vs[1][tid] = g_v[1][ix];
        vs[2][tid] = g_v[2][ix];
        vs[3][tid] = g_v[4][ix];
        vs[4][tid] = 0.5f * g_y[8][ix] / g_colsum[ix] + 0.5f * g_v[7][ix];
    }
    __syncthreads();

    int c = tid & 127, hf = tid >> 7;
    const float* X = g_Xb + ((size_t)g * NPTS + chunk * 128) * DIM;
    float acc[5] = {0.f, 0.f, 0.f, 0.f, 0.f};
    for (int n = hf; n < 128; n += 2) {
        float x = X[(size_t)n * DIM + c];
        #pragma unroll
        for (int tt = 0; tt < 5; tt++) acc[tt] += vs[tt][n] * x;
    }
    #pragma unroll
    for (int tt = 0; tt < 5; tt++)
        g_part[(((g * 16 + chunk) * 5 + tt) * 128 + c) * 2 + hf] = acc[tt];
}

// ---------------------------------------------------------------------------
// Kernel 4b: reduce partials over 16 chunks x 2 halves -> out
// ---------------------------------------------------------------------------
__global__ void __launch_bounds__(640) feats_reduce_kernel(float* __restrict__ out) {
    int g = blockIdx.x;
    int tid = threadIdx.x;
    int t = tid >> 7, c = tid & 127;
    float s = 0.f;
    #pragma unroll
    for (int ch = 0; ch < 16; ch++) {
        const float* p = &g_part[(((g * 16 + ch) * 5 + t) * 128 + c) * 2];
        s += p[0] + p[1];
    }
    out[g * 640 + t * 128 + c] = s;
}

// ---------------------------------------------------------------------------
extern "C" void kernel_launch(void* const* d_in, const int* in_sizes, int n_in,
                              void* d_out, int out_size) {
    const float* pc = (const float*)d_in[0];   // point_clouds [4,2048,128]
    const float* al = (const float*)d_in[1];   // alphas [4,128]
    const float* sg = (const float*)d_in[2];   // sigma scalar
    float* out = (float*)d_out;                // [4, 2560] fp32

    cudaFuncSetAttribute(gram_mma_kernel,
                         cudaFuncAttributeMaxDynamicSharedMemorySize, GRAM_SMEM);

    prep_kernel<<<NG * NPTS, DIM>>>(pc, al);

    dim3 ggrid(136, NG);
    gram_mma_kernel<<<ggrid, 256, GRAM_SMEM>>>(sg);

    dim3 sgrid(136, NG);
    for (int s = 0; s < 8; s++)
        step_tile_kernel<<<sgrid, 256>>>(s);

    dim3 fgrid(16, NG);
    feats_part_kernel<<<fgrid, 256>>>();
    feats_reduce_kernel<<<NG, 640>>>(out);
}